// round 5
// baseline (speedup 1.0000x reference)
#include <cuda_runtime.h>

#define NPL   16384
#define NLVL  8
#define EPL   (NPL * 8)
#define TM    128          // rows per block tile
#define NB    128          // persistent grid, 1 CTA/SM, all co-resident
#define NT    512          // threads per block (16 warps, 4 per SMSP)
#define PITCH 132          // Xs/Gs pitch in floats
#define PBULL 66           // Bs2 pitch in ulonglong (64 cols + pad)

// shared layout (floats)
#define XS_SZ   (64 * PITCH)                 // 8448
#define OFF_XS  0
#define OFF_GS  (XS_SZ)
#define OFF_B2  (2 * XS_SZ)                  // Bs2: 128 * 66 ull = 16896 floats
#define OFF_BL  (OFF_B2 + 128 * PBULL * 2)
#define SMEM_FLOATS (OFF_BL + 64)
#define SMEM_BYTES  (SMEM_FLOATS * 4)        // ~135 KB

__device__ unsigned int g_count = 0;
__device__ unsigned int g_phase = 0;

__device__ __forceinline__ void grid_barrier() {
    __threadfence();
    __syncthreads();
    if (threadIdx.x == 0) {
        volatile unsigned int* ph = &g_phase;
        unsigned int my = *ph;
        unsigned int v = atomicAdd(&g_count, 1u);
        if (v == NB - 1) {
            atomicExch(&g_count, 0u);
            __threadfence();
            atomicAdd(&g_phase, 1u);
        } else {
            while (*ph == my) { }
        }
    }
    __syncthreads();
}

__device__ __forceinline__ float tanh_fast(float v) {
    v = fminf(fmaxf(v, -20.0f), 20.0f);
    float e;
    asm("ex2.approx.f32 %0, %1;" : "=f"(e) : "f"(v * 2.8853900817779268f)); // exp(2v)
    float r;
    asm("rcp.approx.f32 %0, %1;" : "=f"(r) : "f"(e + 1.0f));
    return (e - 1.0f) * r;
}

#define PACK2(d, s) asm("mov.b64 %0, {%1, %1};" : "=l"(d) : "f"(s))
#define FMA2(c, a, bb) asm("fma.rn.f32x2 %0, %1, %2, %0;" : "+l"(c) : "l"(a), "l"(bb))
#define UNPACK2(lo, hi, v) asm("mov.b64 {%0, %1}, %2;" : "=f"(lo), "=f"(hi) : "l"(v))

// One k-step: A (4 rows packed as 2 pairs) from AS, B (4 cols, pre-duplicated) from Bs2.
#define GSTEP(AS, ka, kb) do {                                                     \
    ulonglong2 A = *(const ulonglong2*)&(AS)[(ka) * PITCH + 4 * ty];               \
    const ulonglong2* _bp = (const ulonglong2*)&Bs2[(size_t)(kb) * PBULL + 4 * tx];\
    ulonglong2 Bl = _bp[0];                                                        \
    ulonglong2 Bh = _bp[1];                                                        \
    FMA2(acc[0][0], A.x, Bl.x); FMA2(acc[0][1], A.x, Bl.y);                        \
    FMA2(acc[0][2], A.x, Bh.x); FMA2(acc[0][3], A.x, Bh.y);                        \
    FMA2(acc[1][0], A.y, Bl.x); FMA2(acc[1][1], A.y, Bl.y);                        \
    FMA2(acc[1][2], A.y, Bh.x); FMA2(acc[1][3], A.y, Bh.y);                        \
} while (0)

__global__ void __launch_bounds__(NT, 1)
dag_persistent(const float* __restrict__ x,
               const int*   __restrict__ src,
               const float* __restrict__ Wl,
               const float* __restrict__ bl,
               const float* __restrict__ Wr,
               float*       __restrict__ out)
{
    extern __shared__ float sm[];
    float*              Xs  = sm + OFF_XS;
    float*              Gs  = sm + OFF_GS;
    unsigned long long* Bs2 = (unsigned long long*)(sm + OFF_B2);
    float*              bls = sm + OFF_BL;

    const int t    = threadIdx.x;
    const int b    = blockIdx.x;
    const int lane = t & 31;
    const int w    = t >> 5;        // warp 0..15
    const int tx   = t & 15;        // col group: cols 4tx..4tx+3
    const int ty   = t >> 4;        // row group: rows 4ty..4ty+3  (0..31)
    const int kk   = t & 63;        // x-fill column
    const int g8   = t >> 6;        // x-fill quad phase 0..7

    // ---- one-time: B = [W_r | W_l]^T duplicated into Bs2; bias ----
    for (int idx = t; idx < 64 * 128; idx += NT) {
        int d = idx & 63, k = idx >> 6;
        float v = (k < 64) ? Wr[d * 64 + k] : Wl[d * 64 + (k - 64)];
        float2 f2 = make_float2(v, v);
        *(float2*)&Bs2[(size_t)k * PBULL + d] = f2;
    }
    if (t < 64) bls[t] = bl[t];

    // ---- fill Xs with level-0 x (transposed) ----
    {
        const float* xb = x + (size_t)(b * TM) * 64;
        #pragma unroll
        for (int s = 0; s < 4; s++) {
            int q = g8 + 8 * s;                 // row quad 0..31
            float4 v;
            v.x = xb[(4 * q + 0) * 64 + kk];
            v.y = xb[(4 * q + 1) * 64 + kk];
            v.z = xb[(4 * q + 2) * 64 + kk];
            v.w = xb[(4 * q + 3) * 64 + kk];
            *(float4*)&Xs[kk * PITCH + 4 * q] = v;
        }
    }

    float px[16];

    for (int level = 0; level < NLVL; level++) {
        const int rowbase = level * NPL + b * TM;

        // ---- gather: sum 8 children rows (prev-level out, L2-resident) into Gs ----
        if (level > 0) {
            const int ebase = (level - 1) * EPL + (b * TM) * 8;
            const int col2  = 2 * lane;
            #pragma unroll 2
            for (int rr = 0; rr < 8; rr++) {
                int r = w * 8 + rr;
                const int4* ep = (const int4*)&src[ebase + r * 8];
                int4 c0 = ep[0], c1 = ep[1];
                float a0 = 0.f, a1 = 0.f;
                float2 v;
                v = *(const float2*)(out + (size_t)c0.x * 64 + col2); a0 += v.x; a1 += v.y;
                v = *(const float2*)(out + (size_t)c0.y * 64 + col2); a0 += v.x; a1 += v.y;
                v = *(const float2*)(out + (size_t)c0.z * 64 + col2); a0 += v.x; a1 += v.y;
                v = *(const float2*)(out + (size_t)c0.w * 64 + col2); a0 += v.x; a1 += v.y;
                v = *(const float2*)(out + (size_t)c1.x * 64 + col2); a0 += v.x; a1 += v.y;
                v = *(const float2*)(out + (size_t)c1.y * 64 + col2); a0 += v.x; a1 += v.y;
                v = *(const float2*)(out + (size_t)c1.z * 64 + col2); a0 += v.x; a1 += v.y;
                v = *(const float2*)(out + (size_t)c1.w * 64 + col2); a0 += v.x; a1 += v.y;
                Gs[col2 * PITCH + r]       = a0;
                Gs[(col2 + 1) * PITCH + r] = a1;
            }
        }

        // ---- prefetch next level's x into registers ----
        if (level < NLVL - 1) {
            const float* xb = x + (size_t)((level + 1) * NPL + b * TM) * 64;
            #pragma unroll
            for (int s = 0; s < 4; s++) {
                int q = g8 + 8 * s;
                px[4 * s + 0] = xb[(4 * q + 0) * 64 + kk];
                px[4 * s + 1] = xb[(4 * q + 1) * 64 + kk];
                px[4 * s + 2] = xb[(4 * q + 2) * 64 + kk];
                px[4 * s + 3] = xb[(4 * q + 3) * 64 + kk];
            }
        }
        __syncthreads();   // Gs ready; Xs ready (staged last level)

        // ---- GEMM: [x | agg] @ [W_r | W_l]^T, packed f32x2 ----
        unsigned long long acc[2][4];
        if (level == 0) {
            #pragma unroll
            for (int p = 0; p < 2; p++)
                #pragma unroll
                for (int j = 0; j < 4; j++) acc[p][j] = 0ULL;
        } else {
            float4 bv = *(const float4*)&bls[4 * tx];
            unsigned long long b0, b1, b2, b3;
            PACK2(b0, bv.x); PACK2(b1, bv.y); PACK2(b2, bv.z); PACK2(b3, bv.w);
            acc[0][0] = b0; acc[0][1] = b1; acc[0][2] = b2; acc[0][3] = b3;
            acc[1][0] = b0; acc[1][1] = b1; acc[1][2] = b2; acc[1][3] = b3;
        }

        #pragma unroll 8
        for (int k = 0; k < 64; k++) { GSTEP(Xs, k, k); }
        if (level > 0) {
            #pragma unroll 8
            for (int k = 0; k < 64; k++) { GSTEP(Gs, k, 64 + k); }
        }

        __syncthreads();   // everyone done reading Xs

        // ---- restage prefetched x into Xs for the next level ----
        if (level < NLVL - 1) {
            #pragma unroll
            for (int s = 0; s < 4; s++) {
                int q = g8 + 8 * s;
                float4 v;
                v.x = px[4 * s + 0]; v.y = px[4 * s + 1];
                v.z = px[4 * s + 2]; v.w = px[4 * s + 3];
                *(float4*)&Xs[kk * PITCH + 4 * q] = v;
            }
        }

        // ---- epilogue: tanh + store ----
        float* ob = out + (size_t)rowbase * 64;
        #pragma unroll
        for (int p = 0; p < 2; p++) {
            float lo[4], hi[4];
            #pragma unroll
            for (int j = 0; j < 4; j++) UNPACK2(lo[j], hi[j], acc[p][j]);
            int r0 = 4 * ty + 2 * p;
            float4 v0, v1;
            if (level == 0) {
                v0 = make_float4(lo[0], lo[1], lo[2], lo[3]);
                v1 = make_float4(hi[0], hi[1], hi[2], hi[3]);
            } else {
                v0 = make_float4(tanh_fast(lo[0]), tanh_fast(lo[1]),
                                 tanh_fast(lo[2]), tanh_fast(lo[3]));
                v1 = make_float4(tanh_fast(hi[0]), tanh_fast(hi[1]),
                                 tanh_fast(hi[2]), tanh_fast(hi[3]));
            }
            *(float4*)&ob[(size_t)r0 * 64 + 4 * tx]       = v0;
            *(float4*)&ob[(size_t)(r0 + 1) * 64 + 4 * tx] = v1;
        }

        if (level < NLVL - 1) grid_barrier();
    }
}

extern "C" void kernel_launch(void* const* d_in, const int* in_sizes, int n_in,
                              void* d_out, int out_size)
{
    const float* x   = (const float*)d_in[0];
    const int*   ei  = (const int*)  d_in[1];   // row 0 = src
    const float* Wl  = (const float*)d_in[2];
    const float* bl  = (const float*)d_in[3];
    const float* Wr  = (const float*)d_in[4];
    float*       out = (float*)d_out;

    cudaFuncSetAttribute(dag_persistent,
                         cudaFuncAttributeMaxDynamicSharedMemorySize, SMEM_BYTES);
    dag_persistent<<<NB, NT, SMEM_BYTES>>>(x, ei, Wl, bl, Wr, out);
}

// round 7
// speedup vs baseline: 1.9211x; 1.9211x over previous
#include <cuda_runtime.h>

#define NPL   16384
#define NLVL  8
#define EPL   (NPL * 8)
#define TM    128          // rows per block tile
#define NB    128          // persistent grid, 1 CTA/SM
#define NT    512          // 16 warps, 4 per SMSP
#define PITCH 132          // Xs/Gs pitch in floats
#define PB    68           // Bs pitch in floats

// shared layout (floats)
#define XS_SZ   (64 * PITCH)
#define OFF_XS0 0
#define OFF_XS1 (XS_SZ)
#define OFF_GS  (2 * XS_SZ)
#define OFF_BS  (3 * XS_SZ)
#define OFF_BL  (OFF_BS + 128 * PB)
#define SMEM_FLOATS (OFF_BL + 64)
#define SMEM_BYTES  (SMEM_FLOATS * 4)      // ~136 KB

__device__ unsigned int g_count = 0;
__device__ unsigned int g_phase = 0;

__device__ __forceinline__ void grid_barrier() {
    __threadfence();
    __syncthreads();
    if (threadIdx.x == 0) {
        volatile unsigned int* ph = &g_phase;
        unsigned int my = *ph;
        unsigned int v = atomicAdd(&g_count, 1u);
        if (v == NB - 1) {
            atomicExch(&g_count, 0u);
            __threadfence();
            atomicAdd(&g_phase, 1u);
        } else {
            while (*ph == my) { }
        }
    }
    __syncthreads();
}

__device__ __forceinline__ float tanh_fast(float v) {
    v = fminf(fmaxf(v, -20.0f), 20.0f);
    float e;
    asm("ex2.approx.f32 %0, %1;" : "=f"(e) : "f"(v * 2.8853900817779268f)); // exp(2v)
    float r;
    asm("rcp.approx.f32 %0, %1;" : "=f"(r) : "f"(e + 1.0f));
    return (e - 1.0f) * r;
}

#define PACK2(d, s) asm("mov.b64 %0, {%1, %1};" : "=l"(d) : "f"(s))
#define FMA2(c, a, bb) asm("fma.rn.f32x2 %0, %1, %2, %0;" : "+l"(c) : "l"(a), "l"(bb))
#define UNPACK2(lo, hi, v) asm("mov.b64 {%0, %1}, %2;" : "=f"(lo), "=f"(hi) : "l"(v))

// One k-step: A = 1 LDS.128 (rows 4ty..4ty+3 = 2 pairs, broadcast within warp),
// B = 1 LDS.128 (4 cols) + 4 PACK2 (alu pipe, free), 8 FMA2.
#define GSTEP(AS, ka, kb) do {                                                   \
    ulonglong2 A = *(const ulonglong2*)&(AS)[(ka) * PITCH + 4 * ty];             \
    float4 bq = *(const float4*)&Bs[(kb) * PB + 4 * tx];                         \
    unsigned long long B0, B1, B2, B3;                                           \
    PACK2(B0, bq.x); PACK2(B1, bq.y); PACK2(B2, bq.z); PACK2(B3, bq.w);          \
    FMA2(acc[0][0], A.x, B0); FMA2(acc[0][1], A.x, B1);                          \
    FMA2(acc[0][2], A.x, B2); FMA2(acc[0][3], A.x, B3);                          \
    FMA2(acc[1][0], A.y, B0); FMA2(acc[1][1], A.y, B1);                          \
    FMA2(acc[1][2], A.y, B2); FMA2(acc[1][3], A.y, B3);                          \
} while (0)

__global__ void __launch_bounds__(NT, 1)
dag_persistent(const float* __restrict__ x,
               const int*   __restrict__ src,
               const float* __restrict__ Wl,
               const float* __restrict__ bl,
               const float* __restrict__ Wr,
               float*       __restrict__ out)
{
    extern __shared__ float sm[];
    float* Xs0 = sm + OFF_XS0;
    float* Xs1 = sm + OFF_XS1;
    float* Gs  = sm + OFF_GS;
    float* Bs  = sm + OFF_BS;
    float* bls = sm + OFF_BL;

    const int t    = threadIdx.x;
    const int b    = blockIdx.x;
    const int lane = t & 31;
    const int w    = t >> 5;        // warp 0..15
    const int tx   = t & 15;        // cols 4tx..4tx+3
    const int ty   = t >> 4;        // rows 4ty..4ty+3 (0..31)
    const int kk   = t & 63;        // x-fill column
    const int g8   = t >> 6;        // x-fill quad phase 0..7

    // ---- one-time: B = [W_r | W_l]^T into shared (transposed); bias ----
    for (int idx = t; idx < 64 * 128; idx += NT) {
        int k = idx & 127, d = idx >> 7;
        Bs[k * PB + d] = (k < 64) ? Wr[d * 64 + k] : Wl[d * 64 + (k - 64)];
    }
    if (t < 64) bls[t] = bl[t];

    // ---- fill Xs0 with level-0 x (transposed; float4 STS) ----
    {
        const float* xb = x + (size_t)(b * TM) * 64;
        #pragma unroll
        for (int s = 0; s < 4; s++) {
            int q = g8 + 8 * s;                 // row quad 0..31
            float4 v;
            v.x = xb[(4 * q + 0) * 64 + kk];
            v.y = xb[(4 * q + 1) * 64 + kk];
            v.z = xb[(4 * q + 2) * 64 + kk];
            v.w = xb[(4 * q + 3) * 64 + kk];
            *(float4*)&Xs0[kk * PITCH + 4 * q] = v;
        }
    }

    float px[16];

    for (int level = 0; level < NLVL; level++) {
        float* Xc = (level & 1) ? Xs1 : Xs0;
        float* Xn = (level & 1) ? Xs0 : Xs1;
        const int rowbase = level * NPL + b * TM;

        // ---- gather: sum 8 children rows (prev-level out, L2-resident) into Gs ----
        if (level > 0) {
            const int ebase = (level - 1) * EPL + (b * TM) * 8;
            const int col2  = 2 * lane;
            #pragma unroll 2
            for (int rr = 0; rr < 8; rr++) {
                int r = w * 8 + rr;
                const int4* ep = (const int4*)&src[ebase + r * 8];
                int4 c0 = ep[0], c1 = ep[1];
                float a0 = 0.f, a1 = 0.f;
                float2 v;
                v = *(const float2*)(out + (size_t)c0.x * 64 + col2); a0 += v.x; a1 += v.y;
                v = *(const float2*)(out + (size_t)c0.y * 64 + col2); a0 += v.x; a1 += v.y;
                v = *(const float2*)(out + (size_t)c0.z * 64 + col2); a0 += v.x; a1 += v.y;
                v = *(const float2*)(out + (size_t)c0.w * 64 + col2); a0 += v.x; a1 += v.y;
                v = *(const float2*)(out + (size_t)c1.x * 64 + col2); a0 += v.x; a1 += v.y;
                v = *(const float2*)(out + (size_t)c1.y * 64 + col2); a0 += v.x; a1 += v.y;
                v = *(const float2*)(out + (size_t)c1.z * 64 + col2); a0 += v.x; a1 += v.y;
                v = *(const float2*)(out + (size_t)c1.w * 64 + col2); a0 += v.x; a1 += v.y;
                Gs[col2 * PITCH + r]       = a0;
                Gs[(col2 + 1) * PITCH + r] = a1;
            }
        }

        // ---- prefetch next level's x into registers (hidden behind GEMM) ----
        if (level < NLVL - 1) {
            const float* xb = x + (size_t)((level + 1) * NPL + b * TM) * 64;
            #pragma unroll
            for (int s = 0; s < 4; s++) {
                int q = g8 + 8 * s;
                px[4 * s + 0] = xb[(4 * q + 0) * 64 + kk];
                px[4 * s + 1] = xb[(4 * q + 1) * 64 + kk];
                px[4 * s + 2] = xb[(4 * q + 2) * 64 + kk];
                px[4 * s + 3] = xb[(4 * q + 3) * 64 + kk];
            }
        }
        __syncthreads();   // Gs ready; Xc staged previous iteration

        // ---- GEMM: [x | agg] @ [W_r | W_l]^T, packed f32x2 ----
        unsigned long long acc[2][4];
        if (level == 0) {
            #pragma unroll
            for (int p = 0; p < 2; p++)
                #pragma unroll
                for (int j = 0; j < 4; j++) acc[p][j] = 0ULL;
        } else {
            float4 bv = *(const float4*)&bls[4 * tx];
            unsigned long long b0, b1, b2, b3;
            PACK2(b0, bv.x); PACK2(b1, bv.y); PACK2(b2, bv.z); PACK2(b3, bv.w);
            acc[0][0] = b0; acc[0][1] = b1; acc[0][2] = b2; acc[0][3] = b3;
            acc[1][0] = b0; acc[1][1] = b1; acc[1][2] = b2; acc[1][3] = b3;
        }

        #pragma unroll 8
        for (int k = 0; k < 64; k++) { GSTEP(Xc, k, k); }
        if (level > 0) {
            #pragma unroll 8
            for (int k = 0; k < 64; k++) { GSTEP(Gs, k, 64 + k); }
        }

        // ---- stage prefetched x into the other ping-pong buffer ----
        if (level < NLVL - 1) {
            #pragma unroll
            for (int s = 0; s < 4; s++) {
                int q = g8 + 8 * s;
                float4 v;
                v.x = px[4 * s + 0]; v.y = px[4 * s + 1];
                v.z = px[4 * s + 2]; v.w = px[4 * s + 3];
                *(float4*)&Xn[kk * PITCH + 4 * q] = v;
            }
        }

        // ---- epilogue: (bias already in acc) + fast tanh, store ----
        float* ob = out + (size_t)rowbase * 64;
        #pragma unroll
        for (int p = 0; p < 2; p++) {
            float lo[4], hi[4];
            #pragma unroll
            for (int j = 0; j < 4; j++) UNPACK2(lo[j], hi[j], acc[p][j]);
            int r0 = 4 * ty + 2 * p;
            float4 v0, v1;
            if (level == 0) {
                v0 = make_float4(lo[0], lo[1], lo[2], lo[3]);
                v1 = make_float4(hi[0], hi[1], hi[2], hi[3]);
            } else {
                v0 = make_float4(tanh_fast(lo[0]), tanh_fast(lo[1]),
                                 tanh_fast(lo[2]), tanh_fast(lo[3]));
                v1 = make_float4(tanh_fast(hi[0]), tanh_fast(hi[1]),
                                 tanh_fast(hi[2]), tanh_fast(hi[3]));
            }
            *(float4*)&ob[(size_t)r0 * 64 + 4 * tx]       = v0;
            *(float4*)&ob[(size_t)(r0 + 1) * 64 + 4 * tx] = v1;
        }

        if (level < NLVL - 1) grid_barrier();
    }
}

extern "C" void kernel_launch(void* const* d_in, const int* in_sizes, int n_in,
                              void* d_out, int out_size)
{
    const float* x   = (const float*)d_in[0];
    const int*   ei  = (const int*)  d_in[1];   // row 0 = src
    const float* Wl  = (const float*)d_in[2];
    const float* bl  = (const float*)d_in[3];
    const float* Wr  = (const float*)d_in[4];
    float*       out = (float*)d_out;

    cudaFuncSetAttribute(dag_persistent,
                         cudaFuncAttributeMaxDynamicSharedMemorySize, SMEM_BYTES);
    dag_persistent<<<NB, NT, SMEM_BYTES>>>(x, ei, Wl, bl, Wr, out);
}

// round 8
// speedup vs baseline: 1.9326x; 1.0060x over previous
#include <cuda_runtime.h>

#define NPL   16384
#define NLVL  8
#define EPL   (NPL * 8)
#define TM    128          // rows per block tile
#define NB    128          // persistent grid, 1 CTA/SM
#define NT    512          // 16 warps, 4 per SMSP
#define PITCH 132          // Xs/Gs pitch in floats
#define PB    68           // Bs pitch in floats

// shared layout (floats)
#define XS_SZ   (64 * PITCH)
#define OFF_XS0 0
#define OFF_XS1 (XS_SZ)
#define OFF_GS  (2 * XS_SZ)
#define OFF_BS  (3 * XS_SZ)
#define OFF_BL  (OFF_BS + 128 * PB)
#define SMEM_FLOATS (OFF_BL + 64)
#define SMEM_BYTES  (SMEM_FLOATS * 4)      // ~136 KB

__device__ unsigned int g_count = 0;
__device__ unsigned int g_phase = 0;

__device__ __forceinline__ void grid_barrier() {
    __threadfence();
    __syncthreads();
    if (threadIdx.x == 0) {
        volatile unsigned int* ph = &g_phase;
        unsigned int my = *ph;
        unsigned int v = atomicAdd(&g_count, 1u);
        if (v == NB - 1) {
            atomicExch(&g_count, 0u);
            __threadfence();
            atomicAdd(&g_phase, 1u);
        } else {
            while (*ph == my) { }
        }
    }
    __syncthreads();
}

__device__ __forceinline__ float tanh_fast(float v) {
    v = fminf(fmaxf(v, -20.0f), 20.0f);
    float e;
    asm("ex2.approx.f32 %0, %1;" : "=f"(e) : "f"(v * 2.8853900817779268f)); // exp(2v)
    float r;
    asm("rcp.approx.f32 %0, %1;" : "=f"(r) : "f"(e + 1.0f));
    return (e - 1.0f) * r;
}

#define PACK2(d, s) asm("mov.b64 %0, {%1, %1};" : "=l"(d) : "f"(s))
#define FMA2(c, a, bb) asm("fma.rn.f32x2 %0, %1, %2, %0;" : "+l"(c) : "l"(a), "l"(bb))
#define UNPACK2(lo, hi, v) asm("mov.b64 {%0, %1}, %2;" : "=f"(lo), "=f"(hi) : "l"(v))

// One k-step: A = 1 LDS.128 (rows 4ty..4ty+3, broadcast in warp-half),
// B = 1 LDS.128 + 4 PACK2 (alu pipe), 8 FMA2.
#define GSTEP(AS, ka, kb) do {                                                   \
    ulonglong2 A = *(const ulonglong2*)&(AS)[(ka) * PITCH + 4 * ty];             \
    float4 bq = *(const float4*)&Bs[(kb) * PB + 4 * tx];                         \
    unsigned long long B0, B1, B2, B3;                                           \
    PACK2(B0, bq.x); PACK2(B1, bq.y); PACK2(B2, bq.z); PACK2(B3, bq.w);          \
    FMA2(acc[0][0], A.x, B0); FMA2(acc[0][1], A.x, B1);                          \
    FMA2(acc[0][2], A.x, B2); FMA2(acc[0][3], A.x, B3);                          \
    FMA2(acc[1][0], A.y, B0); FMA2(acc[1][1], A.y, B1);                          \
    FMA2(acc[1][2], A.y, B2); FMA2(acc[1][3], A.y, B3);                          \
} while (0)

__global__ void __launch_bounds__(NT, 1)
dag_persistent(const float* __restrict__ x,
               const int*   __restrict__ src,
               const float* __restrict__ Wl,
               const float* __restrict__ bl,
               const float* __restrict__ Wr,
               float*       __restrict__ out)
{
    extern __shared__ float sm[];
    float* Xs0 = sm + OFF_XS0;
    float* Xs1 = sm + OFF_XS1;
    float* Gs  = sm + OFF_GS;
    float* Bs  = sm + OFF_BS;
    float* bls = sm + OFF_BL;

    const int t    = threadIdx.x;
    const int b    = blockIdx.x;
    const int lane = t & 31;
    const int w    = t >> 5;        // warp 0..15 -> owns rows 8w..8w+7
    const int tx   = t & 15;        // cols 4tx..4tx+3
    const int ty   = t >> 4;        // rows 4ty..4ty+3 (warp w: ty = 2w, 2w+1)
    const int kk   = t & 63;        // x-fill column
    const int g8   = t >> 6;        // x-fill quad phase 0..7

    // ---- one-time: B = [W_r | W_l]^T transposed into shared; bias ----
    for (int idx = t; idx < 64 * 128; idx += NT) {
        int k = idx & 127, d = idx >> 7;
        Bs[k * PB + d] = (k < 64) ? Wr[d * 64 + k] : Wl[d * 64 + (k - 64)];
    }
    if (t < 64) bls[t] = bl[t];

    // ---- fill Xs0 with level-0 x (transposed) ----
    {
        const float* xb = x + (size_t)(b * TM) * 64;
        #pragma unroll
        for (int s = 0; s < 4; s++) {
            int q = g8 + 8 * s;
            float4 v;
            v.x = xb[(4 * q + 0) * 64 + kk];
            v.y = xb[(4 * q + 1) * 64 + kk];
            v.z = xb[(4 * q + 2) * 64 + kk];
            v.w = xb[(4 * q + 3) * 64 + kk];
            *(float4*)&Xs0[kk * PITCH + 4 * q] = v;
        }
    }
    __syncthreads();   // Xs0 + Bs visible to all warps

    float px[16];

    for (int level = 0; level < NLVL; level++) {
        float* Xc = (level & 1) ? Xs1 : Xs0;
        float* Xn = (level & 1) ? Xs0 : Xs1;
        const int rowbase = level * NPL + b * TM;

        // ---- gather: warp w sums 8 children for ITS rows 8w..8w+7 into Gs ----
        // (Gs rows 8w..8w+7 are read back only by warp w -> warp-local dependency)
        if (level > 0) {
            const int ebase = (level - 1) * EPL + (b * TM) * 8;
            const int col2  = 2 * lane;
            #pragma unroll 2
            for (int rr = 0; rr < 8; rr++) {
                int r = w * 8 + rr;
                const int4* ep = (const int4*)&src[ebase + r * 8];
                int4 c0 = ep[0], c1 = ep[1];
                float a0 = 0.f, a1 = 0.f;
                float2 v;
                v = *(const float2*)(out + (size_t)c0.x * 64 + col2); a0 += v.x; a1 += v.y;
                v = *(const float2*)(out + (size_t)c0.y * 64 + col2); a0 += v.x; a1 += v.y;
                v = *(const float2*)(out + (size_t)c0.z * 64 + col2); a0 += v.x; a1 += v.y;
                v = *(const float2*)(out + (size_t)c0.w * 64 + col2); a0 += v.x; a1 += v.y;
                v = *(const float2*)(out + (size_t)c1.x * 64 + col2); a0 += v.x; a1 += v.y;
                v = *(const float2*)(out + (size_t)c1.y * 64 + col2); a0 += v.x; a1 += v.y;
                v = *(const float2*)(out + (size_t)c1.z * 64 + col2); a0 += v.x; a1 += v.y;
                v = *(const float2*)(out + (size_t)c1.w * 64 + col2); a0 += v.x; a1 += v.y;
                Gs[col2 * PITCH + r]       = a0;
                Gs[(col2 + 1) * PITCH + r] = a1;
            }
        }

        // ---- prefetch next level's x (in flight during the GEMM) ----
        if (level < NLVL - 1) {
            const float* xb = x + (size_t)((level + 1) * NPL + b * TM) * 64;
            #pragma unroll
            for (int s = 0; s < 4; s++) {
                int q = g8 + 8 * s;
                px[4 * s + 0] = xb[(4 * q + 0) * 64 + kk];
                px[4 * s + 1] = xb[(4 * q + 1) * 64 + kk];
                px[4 * s + 2] = xb[(4 * q + 2) * 64 + kk];
                px[4 * s + 3] = xb[(4 * q + 3) * 64 + kk];
            }
        }

        // ---- GEMM x-half (Xc staged last level; no sync needed) ----
        unsigned long long acc[2][4];
        if (level == 0) {
            #pragma unroll
            for (int p = 0; p < 2; p++)
                #pragma unroll
                for (int j = 0; j < 4; j++) acc[p][j] = 0ULL;
        } else {
            float4 bv = *(const float4*)&bls[4 * tx];
            unsigned long long b0, b1, b2, b3;
            PACK2(b0, bv.x); PACK2(b1, bv.y); PACK2(b2, bv.z); PACK2(b3, bv.w);
            acc[0][0] = b0; acc[0][1] = b1; acc[0][2] = b2; acc[0][3] = b3;
            acc[1][0] = b0; acc[1][1] = b1; acc[1][2] = b2; acc[1][3] = b3;
        }

        #pragma unroll 8
        for (int k = 0; k < 64; k++) { GSTEP(Xc, k, k); }

        // ---- GEMM g-half: reads only this warp's Gs rows ----
        if (level > 0) {
            __syncwarp();
            #pragma unroll 8
            for (int k = 0; k < 64; k++) { GSTEP(Gs, k, 64 + k); }
        }

        // ---- stage prefetched x into the other ping-pong buffer ----
        // (visible to other warps after the grid barrier's __syncthreads)
        if (level < NLVL - 1) {
            #pragma unroll
            for (int s = 0; s < 4; s++) {
                int q = g8 + 8 * s;
                float4 v;
                v.x = px[4 * s + 0]; v.y = px[4 * s + 1];
                v.z = px[4 * s + 2]; v.w = px[4 * s + 3];
                *(float4*)&Xn[kk * PITCH + 4 * q] = v;
            }
        }

        // ---- epilogue: (bias in acc) + fast tanh, store ----
        float* ob = out + (size_t)rowbase * 64;
        #pragma unroll
        for (int p = 0; p < 2; p++) {
            float lo[4], hi[4];
            #pragma unroll
            for (int j = 0; j < 4; j++) UNPACK2(lo[j], hi[j], acc[p][j]);
            int r0 = 4 * ty + 2 * p;
            float4 v0, v1;
            if (level == 0) {
                v0 = make_float4(lo[0], lo[1], lo[2], lo[3]);
                v1 = make_float4(hi[0], hi[1], hi[2], hi[3]);
            } else {
                v0 = make_float4(tanh_fast(lo[0]), tanh_fast(lo[1]),
                                 tanh_fast(lo[2]), tanh_fast(lo[3]));
                v1 = make_float4(tanh_fast(hi[0]), tanh_fast(hi[1]),
                                 tanh_fast(hi[2]), tanh_fast(hi[3]));
            }
            *(float4*)&ob[(size_t)r0 * 64 + 4 * tx]       = v0;
            *(float4*)&ob[(size_t)(r0 + 1) * 64 + 4 * tx] = v1;
        }

        if (level < NLVL - 1) grid_barrier();
    }
}

extern "C" void kernel_launch(void* const* d_in, const int* in_sizes, int n_in,
                              void* d_out, int out_size)
{
    const float* x   = (const float*)d_in[0];
    const int*   ei  = (const int*)  d_in[1];   // row 0 = src
    const float* Wl  = (const float*)d_in[2];
    const float* bl  = (const float*)d_in[3];
    const float* Wr  = (const float*)d_in[4];
    float*       out = (float*)d_out;

    cudaFuncSetAttribute(dag_persistent,
                         cudaFuncAttributeMaxDynamicSharedMemorySize, SMEM_BYTES);
    dag_persistent<<<NB, NT, SMEM_BYTES>>>(x, ei, Wl, bl, Wr, out);
}

// round 9
// speedup vs baseline: 2.7454x; 1.4206x over previous
#include <cuda_runtime.h>
#include <cuda_bf16.h>
#include <cstdint>

#define NPL   16384
#define NLVL  8
#define EPL   (NPL * 8)
#define TM    128
#define NB    128
#define NT    512
#define PITCHA 136          // bf16 elems per A row (272 B) -> conflict-free ldmatrix

// smem byte offsets
#define OFF_AHI 0                        // 128 x 136 bf16 = 34816 B
#define OFF_ALO 34816
#define OFF_BPK 69632                    // 2 mats x 8 ksteps x 8 ntiles x 32 lanes x uint2 = 32768 B
#define OFF_BL  102400                   // 64 floats
#define SMEM_BYTES 102656

__device__ unsigned int g_count = 0;
__device__ unsigned int g_phase = 0;

__device__ __forceinline__ void grid_barrier() {
    __threadfence();
    __syncthreads();
    if (threadIdx.x == 0) {
        volatile unsigned int* ph = &g_phase;
        unsigned int my = *ph;
        unsigned int v = atomicAdd(&g_count, 1u);
        if (v == NB - 1) {
            atomicExch(&g_count, 0u);
            __threadfence();
            atomicAdd(&g_phase, 1u);
        } else {
            while (*ph == my) { }
        }
    }
    __syncthreads();
}

__device__ __forceinline__ float tanh_fast(float v) {
    v = fminf(fmaxf(v, -20.0f), 20.0f);
    float e;
    asm("ex2.approx.f32 %0, %1;" : "=f"(e) : "f"(v * 2.8853900817779268f)); // exp(2v)
    float r;
    asm("rcp.approx.f32 %0, %1;" : "=f"(r) : "f"(e + 1.0f));
    return (e - 1.0f) * r;
}

__device__ __forceinline__ uint32_t smem_u32(const void* p) {
    uint32_t a;
    asm("{ .reg .u64 t; cvta.to.shared.u64 t, %1; cvt.u32.u64 %0, t; }" : "=r"(a) : "l"(p));
    return a;
}

// split two fp32 into packed bf16x2 hi and bf16x2 lo
__device__ __forceinline__ void split2(float a0, float a1, uint32_t& hi, uint32_t& lo) {
    __nv_bfloat162 h = __floats2bfloat162_rn(a0, a1);
    hi = *reinterpret_cast<uint32_t*>(&h);
    float r0 = a0 - __bfloat162float(h.x);
    float r1 = a1 - __bfloat162float(h.y);
    __nv_bfloat162 l = __floats2bfloat162_rn(r0, r1);
    lo = *reinterpret_cast<uint32_t*>(&l);
}

#define LDSM4(a0, a1, a2, a3, addr)                                              \
    asm volatile("ldmatrix.sync.aligned.m8n8.x4.shared.b16 {%0,%1,%2,%3}, [%4];" \
                 : "=r"(a0), "=r"(a1), "=r"(a2), "=r"(a3) : "r"(addr))

#define MMA(accj, a0, a1, a2, a3, b0, b1)                                        \
    asm volatile("mma.sync.aligned.m16n8k16.row.col.f32.bf16.bf16.f32 "          \
                 "{%0,%1,%2,%3}, {%4,%5,%6,%7}, {%8,%9}, {%0,%1,%2,%3};"         \
                 : "+f"(accj[0]), "+f"(accj[1]), "+f"(accj[2]), "+f"(accj[3])    \
                 : "r"(a0), "r"(a1), "r"(a2), "r"(a3), "r"(b0), "r"(b1))

// one k-step of one term: ldmatrix A tile (16x16 bf16), 4 n-tiles MMA
#define MMA_STEP(abase, mat, k0) do {                                            \
    uint32_t a0, a1, a2, a3;                                                     \
    LDSM4(a0, a1, a2, a3, (abase) + (uint32_t)(k0) * 2u);                        \
    const uint2* bp = Bpk + (((size_t)(mat) * 8 + ((k0) >> 4)) * 8 + 4 * ng) * 32 + lane; \
    uint2 bb0 = bp[0];                                                           \
    uint2 bb1 = bp[32];                                                          \
    uint2 bb2 = bp[64];                                                          \
    uint2 bb3 = bp[96];                                                          \
    MMA(acc[0], a0, a1, a2, a3, bb0.x, bb0.y);                                   \
    MMA(acc[1], a0, a1, a2, a3, bb1.x, bb1.y);                                   \
    MMA(acc[2], a0, a1, a2, a3, bb2.x, bb2.y);                                   \
    MMA(acc[3], a0, a1, a2, a3, bb3.x, bb3.y);                                   \
} while (0)

__global__ void __launch_bounds__(NT, 1)
dag_mma(const float* __restrict__ x,
        const int*   __restrict__ src,
        const float* __restrict__ Wl,
        const float* __restrict__ bl,
        const float* __restrict__ Wr,
        float*       __restrict__ out)
{
    extern __shared__ char smem[];
    __nv_bfloat16* Ahi = (__nv_bfloat16*)(smem + OFF_AHI);
    __nv_bfloat16* Alo = (__nv_bfloat16*)(smem + OFF_ALO);
    const uint2*   Bpk = (const uint2*)(smem + OFF_BPK);
    uint2*         BpkW = (uint2*)(smem + OFF_BPK);
    float*         bls = (float*)(smem + OFF_BL);
    const uint32_t sb  = smem_u32(smem);

    const int t    = threadIdx.x;
    const int b    = blockIdx.x;
    const int lane = t & 31;
    const int w    = t >> 5;
    const int g    = lane >> 2;     // frag group 0..7
    const int tig  = lane & 3;      // thread in group
    const int mg   = w >> 1;        // m-group 0..7: rows 16mg..16mg+15
    const int ng   = w & 1;         // n-group 0..1: cols 32ng..32ng+31

    // ---- one-time: prepack B fragments (hi & lo splits) + bias ----
    {
        #pragma unroll
        for (int it = 0; it < 8; it++) {
            int idx  = t + it * NT;          // 0..4095
            int ln   = idx & 31;
            int tile = idx >> 5;             // 0..127
            int mat  = tile >> 6;            // 0 = hi, 1 = lo
            int s    = (tile >> 3) & 7;      // kstep 0..7
            int j    = tile & 7;             // n-tile 0..7
            int gg   = ln >> 2, tg = ln & 3;
            int n    = 8 * j + gg;
            int k0   = 16 * s + 2 * tg;
            auto Wsrc = [&](int kk) {
                return (kk < 64) ? Wr[n * 64 + kk] : Wl[n * 64 + kk - 64];
            };
            float v00 = Wsrc(k0),     v01 = Wsrc(k0 + 1);
            float v10 = Wsrc(k0 + 8), v11 = Wsrc(k0 + 9);
            uint32_t h0, l0, h1, l1;
            split2(v00, v01, h0, l0);
            split2(v10, v11, h1, l1);
            BpkW[(size_t)tile * 32 + ln] = (mat == 0) ? make_uint2(h0, h1) : make_uint2(l0, l1);
        }
        if (t < 64) bls[t] = bl[t];
    }
    __syncthreads();

    // ldmatrix per-thread base addresses (rows 16mg.., k-offset by lane)
    const int row_l = lane & 15;
    const int kof   = (lane >> 4) << 3;
    const uint32_t aHiBase = sb + OFF_AHI + (uint32_t)((16 * mg + row_l) * PITCHA + kof) * 2u;
    const uint32_t aLoBase = sb + OFF_ALO + (uint32_t)((16 * mg + row_l) * PITCHA + kof) * 2u;

    for (int level = 0; level < NLVL; level++) {
        const int rowbase = level * NPL + b * TM;

        // ---- fill A cols [0,64): bf16 hi/lo split of x rows ----
        {
            const float* xb = x + (size_t)rowbase * 64;
            #pragma unroll
            for (int it = 0; it < 8; it++) {
                int idx = t + it * NT;           // 4096 pair-slots
                int r = idx >> 5, c = (idx & 31) * 2;
                float2 v = *(const float2*)(xb + r * 64 + c);
                uint32_t hi, lo;
                split2(v.x, v.y, hi, lo);
                *(uint32_t*)&Ahi[r * PITCHA + c] = hi;
                *(uint32_t*)&Alo[r * PITCHA + c] = lo;
            }
        }

        // ---- fill A cols [64,128): gather-sum of 8 children, split to bf16 ----
        if (level > 0) {
            const int ebase = (level - 1) * EPL + (b * TM) * 8;
            const int col2  = 2 * lane;
            #pragma unroll 2
            for (int rr = 0; rr < 8; rr++) {
                int r = w * 8 + rr;
                const int4* ep = (const int4*)&src[ebase + r * 8];
                int4 c0 = ep[0], c1 = ep[1];
                float a0 = 0.f, a1 = 0.f;
                float2 v;
                v = *(const float2*)(out + (size_t)c0.x * 64 + col2); a0 += v.x; a1 += v.y;
                v = *(const float2*)(out + (size_t)c0.y * 64 + col2); a0 += v.x; a1 += v.y;
                v = *(const float2*)(out + (size_t)c0.z * 64 + col2); a0 += v.x; a1 += v.y;
                v = *(const float2*)(out + (size_t)c0.w * 64 + col2); a0 += v.x; a1 += v.y;
                v = *(const float2*)(out + (size_t)c1.x * 64 + col2); a0 += v.x; a1 += v.y;
                v = *(const float2*)(out + (size_t)c1.y * 64 + col2); a0 += v.x; a1 += v.y;
                v = *(const float2*)(out + (size_t)c1.z * 64 + col2); a0 += v.x; a1 += v.y;
                v = *(const float2*)(out + (size_t)c1.w * 64 + col2); a0 += v.x; a1 += v.y;
                uint32_t hi, lo;
                split2(a0, a1, hi, lo);
                *(uint32_t*)&Ahi[r * PITCHA + 64 + col2] = hi;
                *(uint32_t*)&Alo[r * PITCHA + 64 + col2] = lo;
            }
        }
        __syncthreads();

        // ---- accumulators: bias folded in (levels > 0) ----
        float acc[4][4];
        if (level == 0) {
            #pragma unroll
            for (int j = 0; j < 4; j++)
                #pragma unroll
                for (int q = 0; q < 4; q++) acc[j][q] = 0.f;
        } else {
            #pragma unroll
            for (int j = 0; j < 4; j++) {
                float b0 = bls[32 * ng + 8 * j + 2 * tig];
                float b1 = bls[32 * ng + 8 * j + 2 * tig + 1];
                acc[j][0] = b0; acc[j][1] = b1; acc[j][2] = b0; acc[j][3] = b1;
            }
        }

        // ---- MMA: 3-term bf16 split, x-half (k 0..63) + gather-half (k 64..127) ----
        #pragma unroll
        for (int s4 = 0; s4 < 4; s4++) MMA_STEP(aHiBase, 0, 16 * s4);          // Ahi*Bhi
        #pragma unroll
        for (int s4 = 0; s4 < 4; s4++) MMA_STEP(aHiBase, 1, 16 * s4);          // Ahi*Blo
        #pragma unroll
        for (int s4 = 0; s4 < 4; s4++) MMA_STEP(aLoBase, 0, 16 * s4);          // Alo*Bhi
        if (level > 0) {
            #pragma unroll
            for (int s4 = 0; s4 < 4; s4++) MMA_STEP(aHiBase, 0, 64 + 16 * s4);
            #pragma unroll
            for (int s4 = 0; s4 < 4; s4++) MMA_STEP(aHiBase, 1, 64 + 16 * s4);
            #pragma unroll
            for (int s4 = 0; s4 < 4; s4++) MMA_STEP(aLoBase, 0, 64 + 16 * s4);
        }

        // ---- epilogue: tanh (levels > 0) + store ----
        {
            float* ob = out + (size_t)(rowbase + 16 * mg + g) * 64;
            #pragma unroll
            for (int j = 0; j < 4; j++) {
                int colb = 32 * ng + 8 * j + 2 * tig;
                float2 p0, p1;
                if (level == 0) {
                    p0 = make_float2(acc[j][0], acc[j][1]);
                    p1 = make_float2(acc[j][2], acc[j][3]);
                } else {
                    p0 = make_float2(tanh_fast(acc[j][0]), tanh_fast(acc[j][1]));
                    p1 = make_float2(tanh_fast(acc[j][2]), tanh_fast(acc[j][3]));
                }
                *(float2*)(ob + colb)           = p0;   // row 16mg+g
                *(float2*)(ob + 8 * 64 + colb)  = p1;   // row 16mg+g+8
            }
        }

        if (level < NLVL - 1) grid_barrier();
    }
}

extern "C" void kernel_launch(void* const* d_in, const int* in_sizes, int n_in,
                              void* d_out, int out_size)
{
    const float* x   = (const float*)d_in[0];
    const int*   ei  = (const int*)  d_in[1];   // row 0 = src
    const float* Wl  = (const float*)d_in[2];
    const float* bl  = (const float*)d_in[3];
    const float* Wr  = (const float*)d_in[4];
    float*       out = (float*)d_out;

    cudaFuncSetAttribute(dag_mma, cudaFuncAttributeMaxDynamicSharedMemorySize, SMEM_BYTES);
    dag_mma<<<NB, NT, SMEM_BYTES>>>(x, ei, Wl, bl, Wr, out);
}

// round 10
// speedup vs baseline: 2.7623x; 1.0062x over previous
#include <cuda_runtime.h>
#include <cuda_bf16.h>
#include <cstdint>

#define NPL   16384
#define NLVL  8
#define EPL   (NPL * 8)
#define TM    128
#define NB    128
#define NT    512
#define PITCHA 136          // bf16 elems per A row (272 B) -> conflict-free ldmatrix

// smem byte offsets
#define OFF_AHI 0                        // 128 x 136 bf16 = 34816 B
#define OFF_ALO 34816
#define OFF_BPK 69632                    // 2 x 8 x 8 x 32 x uint2 = 32768 B
#define OFF_BL  102400                   // 64 floats
#define OFF_IDX 102656                   // 2 x 4096 B index double buffer
#define SMEM_BYTES (OFF_IDX + 8192)

__device__ unsigned int g_count = 0;
__device__ unsigned int g_phase = 0;

__device__ __forceinline__ void grid_barrier() {
    __threadfence();
    __syncthreads();
    if (threadIdx.x == 0) {
        volatile unsigned int* ph = &g_phase;
        unsigned int my = *ph;
        unsigned int v = atomicAdd(&g_count, 1u);
        if (v == NB - 1) {
            atomicExch(&g_count, 0u);
            __threadfence();
            atomicAdd(&g_phase, 1u);
        } else {
            while (*ph == my) { }
        }
    }
    __syncthreads();
}

__device__ __forceinline__ float tanh_fast(float v) {
    v = fminf(fmaxf(v, -20.0f), 20.0f);
    float e;
    asm("ex2.approx.f32 %0, %1;" : "=f"(e) : "f"(v * 2.8853900817779268f)); // exp(2v)
    float r;
    asm("rcp.approx.f32 %0, %1;" : "=f"(r) : "f"(e + 1.0f));
    return (e - 1.0f) * r;
}

__device__ __forceinline__ uint32_t smem_u32(const void* p) {
    uint32_t a;
    asm("{ .reg .u64 t; cvta.to.shared.u64 t, %1; cvt.u32.u64 %0, t; }" : "=r"(a) : "l"(p));
    return a;
}

__device__ __forceinline__ void split2(float a0, float a1, uint32_t& hi, uint32_t& lo) {
    __nv_bfloat162 h = __floats2bfloat162_rn(a0, a1);
    hi = *reinterpret_cast<uint32_t*>(&h);
    float r0 = a0 - __bfloat162float(h.x);
    float r1 = a1 - __bfloat162float(h.y);
    __nv_bfloat162 l = __floats2bfloat162_rn(r0, r1);
    lo = *reinterpret_cast<uint32_t*>(&l);
}

#define CP_ASYNC16(saddr, gptr) \
    asm volatile("cp.async.cg.shared.global [%0], [%1], 16;" :: "r"(saddr), "l"(gptr))

#define LDSM4(a0, a1, a2, a3, addr)                                              \
    asm volatile("ldmatrix.sync.aligned.m8n8.x4.shared.b16 {%0,%1,%2,%3}, [%4];" \
                 : "=r"(a0), "=r"(a1), "=r"(a2), "=r"(a3) : "r"(addr))

#define MMA(accj, a0, a1, a2, a3, b0, b1)                                        \
    asm volatile("mma.sync.aligned.m16n8k16.row.col.f32.bf16.bf16.f32 "          \
                 "{%0,%1,%2,%3}, {%4,%5,%6,%7}, {%8,%9}, {%0,%1,%2,%3};"         \
                 : "+f"(accj[0]), "+f"(accj[1]), "+f"(accj[2]), "+f"(accj[3])    \
                 : "r"(a0), "r"(a1), "r"(a2), "r"(a3), "r"(b0), "r"(b1))

#define MMA_STEP(abase, mat, k0) do {                                            \
    uint32_t a0, a1, a2, a3;                                                     \
    LDSM4(a0, a1, a2, a3, (abase) + (uint32_t)(k0) * 2u);                        \
    const uint2* bp = Bpk + (((size_t)(mat) * 8 + ((k0) >> 4)) * 8 + 4 * ng) * 32 + lane; \
    uint2 bb0 = bp[0];                                                           \
    uint2 bb1 = bp[32];                                                          \
    uint2 bb2 = bp[64];                                                          \
    uint2 bb3 = bp[96];                                                          \
    MMA(acc[0], a0, a1, a2, a3, bb0.x, bb0.y);                                   \
    MMA(acc[1], a0, a1, a2, a3, bb1.x, bb1.y);                                   \
    MMA(acc[2], a0, a1, a2, a3, bb2.x, bb2.y);                                   \
    MMA(acc[3], a0, a1, a2, a3, bb3.x, bb3.y);                                   \
} while (0)

__global__ void __launch_bounds__(NT, 1)
dag_mma(const float* __restrict__ x,
        const int*   __restrict__ src,
        const float* __restrict__ Wl,
        const float* __restrict__ bl,
        const float* __restrict__ Wr,
        float*       __restrict__ out)
{
    extern __shared__ char smem[];
    __nv_bfloat16* Ahi  = (__nv_bfloat16*)(smem + OFF_AHI);
    __nv_bfloat16* Alo  = (__nv_bfloat16*)(smem + OFF_ALO);
    const uint2*   Bpk  = (const uint2*)(smem + OFF_BPK);
    uint2*         BpkW = (uint2*)(smem + OFF_BPK);
    float*         bls  = (float*)(smem + OFF_BL);
    const uint32_t sb   = smem_u32(smem);

    const int t    = threadIdx.x;
    const int b    = blockIdx.x;
    const int lane = t & 31;
    const int w    = t >> 5;
    const int tig  = lane & 3;
    const int g    = lane >> 2;
    const int mg   = w >> 1;        // rows 16mg..16mg+15
    const int ng   = w & 1;         // cols 32ng..32ng+31

    // ---- one-time: prepack B fragments (hi & lo) + bias ----
    {
        #pragma unroll
        for (int it = 0; it < 8; it++) {
            int idx  = t + it * NT;
            int ln   = idx & 31;
            int tile = idx >> 5;
            int mat  = tile >> 6;
            int s    = (tile >> 3) & 7;
            int j    = tile & 7;
            int gg   = ln >> 2, tg = ln & 3;
            int n    = 8 * j + gg;
            int k0   = 16 * s + 2 * tg;
            auto Wsrc = [&](int kk) {
                return (kk < 64) ? Wr[n * 64 + kk] : Wl[n * 64 + kk - 64];
            };
            float v00 = Wsrc(k0),     v01 = Wsrc(k0 + 1);
            float v10 = Wsrc(k0 + 8), v11 = Wsrc(k0 + 9);
            uint32_t h0, l0, h1, l1;
            split2(v00, v01, h0, l0);
            split2(v10, v11, h1, l1);
            BpkW[(size_t)tile * 32 + ln] = (mat == 0) ? make_uint2(h0, h1) : make_uint2(l0, l1);
        }
        if (t < 64) bls[t] = bl[t];
    }

    // ---- stage level-0 x into A cols [0,64) ----
    {
        const float* xb = x + (size_t)(b * TM) * 64;
        #pragma unroll
        for (int it = 0; it < 8; it++) {
            int idx = t + it * NT;
            int r = idx >> 5, c = (idx & 31) * 2;
            float2 v = *(const float2*)(xb + r * 64 + c);
            uint32_t hi, lo;
            split2(v.x, v.y, hi, lo);
            *(uint32_t*)&Ahi[r * PITCHA + c] = hi;
            *(uint32_t*)&Alo[r * PITCHA + c] = lo;
        }
    }

    // ---- prefetch level-1 edge indices into idx buffer 1 ----
    if (t < 256) {
        const char* gp = (const char*)(src + (size_t)b * TM * 8) + t * 16;
        CP_ASYNC16(sb + OFF_IDX + 4096 + t * 16, gp);
    }
    asm volatile("cp.async.commit_group;" ::: "memory");
    __syncthreads();

    const int row_l = lane & 15;
    const int kof   = (lane >> 4) << 3;
    const uint32_t aHiBase = sb + OFF_AHI + (uint32_t)((16 * mg + row_l) * PITCHA + kof) * 2u;
    const uint32_t aLoBase = sb + OFF_ALO + (uint32_t)((16 * mg + row_l) * PITCHA + kof) * 2u;

    float px[16];

    for (int level = 0; level < NLVL; level++) {
        const int rowbase = level * NPL + b * TM;

        // ---- gather: idx from smem (prefetched), data from L2; warp-local rows ----
        if (level > 0) {
            asm volatile("cp.async.wait_group 0;" ::: "memory");
            __syncthreads();   // idx buffer visible to all threads
            const int4* idxp = (const int4*)(smem + OFF_IDX + (level & 1) * 4096);
            const int col2 = 2 * lane;
            #pragma unroll 4
            for (int rr = 0; rr < 8; rr++) {
                int r = w * 8 + rr;
                int4 c0 = idxp[r * 2];
                int4 c1 = idxp[r * 2 + 1];
                float a0 = 0.f, a1 = 0.f;
                float2 v;
                v = *(const float2*)(out + (size_t)c0.x * 64 + col2); a0 += v.x; a1 += v.y;
                v = *(const float2*)(out + (size_t)c0.y * 64 + col2); a0 += v.x; a1 += v.y;
                v = *(const float2*)(out + (size_t)c0.z * 64 + col2); a0 += v.x; a1 += v.y;
                v = *(const float2*)(out + (size_t)c0.w * 64 + col2); a0 += v.x; a1 += v.y;
                v = *(const float2*)(out + (size_t)c1.x * 64 + col2); a0 += v.x; a1 += v.y;
                v = *(const float2*)(out + (size_t)c1.y * 64 + col2); a0 += v.x; a1 += v.y;
                v = *(const float2*)(out + (size_t)c1.z * 64 + col2); a0 += v.x; a1 += v.y;
                v = *(const float2*)(out + (size_t)c1.w * 64 + col2); a0 += v.x; a1 += v.y;
                uint32_t hi, lo;
                split2(a0, a1, hi, lo);
                *(uint32_t*)&Ahi[r * PITCHA + 64 + col2] = hi;
                *(uint32_t*)&Alo[r * PITCHA + 64 + col2] = lo;
            }
        }

        // ---- prefetch next level: edge indices (cp.async) + x rows (registers) ----
        if (level < NLVL - 1) {
            if (t < 256) {
                const char* gp = (const char*)(src + (size_t)level * EPL + (size_t)b * TM * 8) + t * 16;
                CP_ASYNC16(sb + OFF_IDX + ((level + 1) & 1) * 4096 + t * 16, gp);
            }
            asm volatile("cp.async.commit_group;" ::: "memory");

            const float* xb = x + (size_t)((level + 1) * NPL + b * TM) * 64;
            #pragma unroll
            for (int it = 0; it < 8; it++) {
                int idx = t + it * NT;
                int r = idx >> 5, c = (idx & 31) * 2;
                float2 v = *(const float2*)(xb + r * 64 + c);
                px[2 * it]     = v.x;
                px[2 * it + 1] = v.y;
            }
        }
        __syncthreads();   // gather results visible for MMA

        // ---- accumulators (bias folded in for levels > 0) ----
        float acc[4][4];
        if (level == 0) {
            #pragma unroll
            for (int j = 0; j < 4; j++)
                #pragma unroll
                for (int q = 0; q < 4; q++) acc[j][q] = 0.f;
        } else {
            #pragma unroll
            for (int j = 0; j < 4; j++) {
                float b0 = bls[32 * ng + 8 * j + 2 * tig];
                float b1 = bls[32 * ng + 8 * j + 2 * tig + 1];
                acc[j][0] = b0; acc[j][1] = b1; acc[j][2] = b0; acc[j][3] = b1;
            }
        }

        // ---- MMA: 3-term bf16 split ----
        #pragma unroll
        for (int s4 = 0; s4 < 4; s4++) MMA_STEP(aHiBase, 0, 16 * s4);
        #pragma unroll
        for (int s4 = 0; s4 < 4; s4++) MMA_STEP(aHiBase, 1, 16 * s4);
        #pragma unroll
        for (int s4 = 0; s4 < 4; s4++) MMA_STEP(aLoBase, 0, 16 * s4);
        if (level > 0) {
            #pragma unroll
            for (int s4 = 0; s4 < 4; s4++) MMA_STEP(aHiBase, 0, 64 + 16 * s4);
            #pragma unroll
            for (int s4 = 0; s4 < 4; s4++) MMA_STEP(aHiBase, 1, 64 + 16 * s4);
            #pragma unroll
            for (int s4 = 0; s4 < 4; s4++) MMA_STEP(aLoBase, 0, 64 + 16 * s4);
        }

        // ---- epilogue ----
        {
            float* ob = out + (size_t)(rowbase + 16 * mg + g) * 64;
            #pragma unroll
            for (int j = 0; j < 4; j++) {
                int colb = 32 * ng + 8 * j + 2 * tig;
                float2 p0, p1;
                if (level == 0) {
                    p0 = make_float2(acc[j][0], acc[j][1]);
                    p1 = make_float2(acc[j][2], acc[j][3]);
                } else {
                    p0 = make_float2(tanh_fast(acc[j][0]), tanh_fast(acc[j][1]));
                    p1 = make_float2(tanh_fast(acc[j][2]), tanh_fast(acc[j][3]));
                }
                *(float2*)(ob + colb)          = p0;
                *(float2*)(ob + 8 * 64 + colb) = p1;
            }
        }

        if (level < NLVL - 1) {
            grid_barrier();
            // stage prefetched x for next level (all warps past MMA after barrier)
            #pragma unroll
            for (int it = 0; it < 8; it++) {
                int idx = t + it * NT;
                int r = idx >> 5, c = (idx & 31) * 2;
                uint32_t hi, lo;
                split2(px[2 * it], px[2 * it + 1], hi, lo);
                *(uint32_t*)&Ahi[r * PITCHA + c] = hi;
                *(uint32_t*)&Alo[r * PITCHA + c] = lo;
            }
        }
    }
}

extern "C" void kernel_launch(void* const* d_in, const int* in_sizes, int n_in,
                              void* d_out, int out_size)
{
    const float* x   = (const float*)d_in[0];
    const int*   ei  = (const int*)  d_in[1];   // row 0 = src
    const float* Wl  = (const float*)d_in[2];
    const float* bl  = (const float*)d_in[3];
    const float* Wr  = (const float*)d_in[4];
    float*       out = (float*)d_out;

    cudaFuncSetAttribute(dag_mma, cudaFuncAttributeMaxDynamicSharedMemorySize, SMEM_BYTES);
    dag_mma<<<NB, NT, SMEM_BYTES>>>(x, ei, Wl, bl, Wr, out);
}